// round 3
// baseline (speedup 1.0000x reference)
#include <cuda_runtime.h>

// BatchBlur: per-sample 15x15 depthwise blur with reflect pad.
// x: (32,3,512,512) f32, kernel: (32,15,15) f32, out: (32,3,512,512) f32.

#define BB 32
#define CC 3
#define HH 512
#define WW 512
#define LL 15
#define PP 7

#define TW 128                 // output cols per CTA
#define TH 32                  // output rows per CTA
#define IN_ROWS (TH + LL - 1)  // 46
#define ROW_F 142              // floats per smem tile row (TW + 14)

typedef unsigned long long u64;

__device__ __forceinline__ void ffma2(u64& acc, u64 a, u64 b) {
    // packed fp32 FMA: acc.lo += a.lo*b.lo ; acc.hi += a.hi*b.hi
    asm("fma.rn.f32x2 %0, %1, %2, %0;" : "+l"(acc) : "l"(a), "l"(b));
}

// build pair {a.hi, b.lo}
__device__ __forceinline__ u64 hilo(u64 a, u64 b) {
    u64 r;
    asm("{\n\t"
        ".reg .b32 alo, ahi, blo, bhi;\n\t"
        "mov.b64 {alo, ahi}, %1;\n\t"
        "mov.b64 {blo, bhi}, %2;\n\t"
        "mov.b64 %0, {ahi, blo};\n\t"
        "}"
        : "=l"(r) : "l"(a), "l"(b));
    return r;
}

// One input row's contribution to one or two output rows.
// Two passes: even dx on the raw pair window, then shift the window in place
// by one float and do odd dx. Peak live pairs = 15 (vs 29 before).
template <bool DO0, bool DO1>
__device__ __forceinline__ void row_step(const char* rowp, const unsigned* offB,
                                         const u64* k0, const u64* k1,
                                         u64* acc0, u64* acc1) {
    u64 w[15];
#pragma unroll
    for (int c = 0; c < 15; c++)
        w[c] = *reinterpret_cast<const u64*>(rowp + offB[c]);

    // even taps: dx = 2e
#pragma unroll
    for (int e = 0; e < 8; e++) {
        u64 kk0 = 0, kk1 = 0;
        if (DO0) kk0 = k0[2 * e];
        if (DO1) kk1 = k1[2 * e];
#pragma unroll
        for (int i = 0; i < 8; i++) {
            if (DO0) ffma2(acc0[i], w[e + i], kk0);
            if (DO1) ffma2(acc1[i], w[e + i], kk1);
        }
    }

    // shift window one float left, in place (increasing c keeps sources valid)
#pragma unroll
    for (int c = 0; c < 14; c++)
        w[c] = hilo(w[c], w[c + 1]);

    // odd taps: dx = 2o + 1
#pragma unroll
    for (int o = 0; o < 7; o++) {
        u64 kk0 = 0, kk1 = 0;
        if (DO0) kk0 = k0[2 * o + 1];
        if (DO1) kk1 = k1[2 * o + 1];
#pragma unroll
        for (int i = 0; i < 8; i++) {
            if (DO0) ffma2(acc0[i], w[o + i], kk0);
            if (DO1) ffma2(acc1[i], w[o + i], kk1);
        }
    }
}

__global__ __launch_bounds__(128, 4) void batchblur_kernel(
    const float* __restrict__ x, const float* __restrict__ ker,
    float* __restrict__ out) {
    __shared__ __align__(16) float s_in[IN_ROWS * ROW_F];
    __shared__ __align__(8) u64 s_k[LL * LL];   // taps duplicated lo/hi

    const int tid = threadIdx.x;
    const int tx = tid & 7;    // 8 threads across x, 16 px each
    const int ty = tid >> 3;   // 16 threads across y, 2 rows each

    const int x0 = blockIdx.x * TW;
    const int y0 = blockIdx.y * TH;
    const int img = blockIdx.z;   // b*3 + c
    const int b = img / CC;

    const float* xin = x + (size_t)img * (HH * WW);

    // kernel taps, duplicated into both f32x2 halves for broadcast
    for (int i = tid; i < LL * LL; i += 128) {
        float v = ker[b * (LL * LL) + i];
        float2 d = make_float2(v, v);
        s_k[i] = *reinterpret_cast<const u64*>(&d);
    }

    // input tile load: reflect pad + pair-granularity XOR swizzle
    for (int idx = tid; idx < IN_ROWS * ROW_F; idx += 128) {
        int r = idx / ROW_F;
        int f = idx - r * ROW_F;
        int gy = y0 + r - PP;
        gy = gy < 0 ? -gy : (gy >= HH ? 2 * HH - 2 - gy : gy);
        int gx = x0 + f - PP;
        gx = gx < 0 ? -gx : (gx >= WW ? 2 * WW - 2 - gx : gx);
        float v = xin[gy * WW + gx];
        int p = f >> 1;
        int q = p ^ ((p >> 3) & 7);
        s_in[r * ROW_F + (q << 1) + (f & 1)] = v;
    }
    __syncthreads();

    // precomputed swizzled BYTE offsets of this thread's 15 window pairs
    unsigned offB[15];
#pragma unroll
    for (int c = 0; c < 15; c++) {
        int q;
        if (c < 8) {
            q = (tx << 3) | (c ^ tx);
        } else {
            int t1 = tx + 1;
            q = (t1 << 3) + ((c - 8) ^ (t1 & 7));
        }
        offB[c] = (unsigned)(q << 3);   // q pairs * 8 bytes
    }

    u64 acc0[8], acc1[8];
#pragma unroll
    for (int i = 0; i < 8; i++) { acc0[i] = 0ull; acc1[i] = 0ull; }

    const int R0 = 2 * ty;   // first input row of this thread's window
    const char* rowp = reinterpret_cast<const char*>(s_in + (size_t)R0 * ROW_F);

    // rr = 0: only out-row0 (kernel row 0)
    row_step<true, false>(rowp, offB, &s_k[0], &s_k[0], acc0, acc1);
    rowp += ROW_F * 4;
#pragma unroll 1
    for (int rr = 1; rr < 15; rr++) {
        row_step<true, true>(rowp, offB, &s_k[rr * 15], &s_k[(rr - 1) * 15],
                             acc0, acc1);
        rowp += ROW_F * 4;
    }
    // rr = 15: only out-row1 (kernel row 14)
    row_step<false, true>(rowp, offB, &s_k[0], &s_k[14 * 15], acc0, acc1);

    // stage outputs in smem (reuse tile), then write coalesced
    __syncthreads();
    float* s_out = s_in;   // 128*32 = 4096 floats <= IN_ROWS*ROW_F
#pragma unroll
    for (int i = 0; i < 8; i++) {
        *reinterpret_cast<u64*>(&s_out[(2 * ty) * TW + 16 * tx + 2 * i]) = acc0[i];
        *reinterpret_cast<u64*>(&s_out[(2 * ty + 1) * TW + 16 * tx + 2 * i]) = acc1[i];
    }
    __syncthreads();

    float* obase = out + (size_t)img * (HH * WW) + (size_t)y0 * WW + x0;
    const int V = (TW * TH) / 4;   // 1024 float4
#pragma unroll
    for (int v = tid; v < V; v += 128) {
        int r = v >> 5;              // TW/4 = 32 float4 per row
        int cidx = v & 31;
        float4 val = reinterpret_cast<const float4*>(s_out)[v];
        *reinterpret_cast<float4*>(obase + (size_t)r * WW + cidx * 4) = val;
    }
}

extern "C" void kernel_launch(void* const* d_in, const int* in_sizes, int n_in,
                              void* d_out, int out_size) {
    const float* x = (const float*)d_in[0];
    const float* k = (const float*)d_in[1];
    float* out = (float*)d_out;
    dim3 grid(WW / TW, HH / TH, BB * CC);
    batchblur_kernel<<<grid, 128>>>(x, k, out);
}

// round 4
// speedup vs baseline: 2.0929x; 2.0929x over previous
#include <cuda_runtime.h>

// BatchBlur: per-sample 15x15 depthwise blur with reflect pad.
// x: (32,3,512,512) f32, kernel: (32,15,15) f32, out: (32,3,512,512) f32.
// Scalar-FFMA version: FP32 FMAs dual-issue across fma+alu pipes on sm_103a,
// so the ceiling is 1 FFMA/cyc/SMSP; optimize issue density + efficiency.

#define BB 32
#define CC 3
#define HH 512
#define WW 512
#define LL 15
#define PP 7

#define TW 128                  // output cols per CTA
#define TH 16                   // output rows per CTA
#define IN_ROWS (TH + LL - 1)   // 30
#define CH_ROW 41               // 16B chunks per smem row (odd -> 2-row bank shift)
#define ROW_F (CH_ROW * 4)      // 164 floats per smem row
#define LOAD_F 148              // floats actually loaded per row (need 142)

__device__ __forceinline__ int reflect_idx(int i, int n) {
    i = i < 0 ? -i : i;
    return i >= n ? 2 * n - 2 - i : i;
}

__global__ __launch_bounds__(128) void batchblur_kernel(
    const float* __restrict__ x, const float* __restrict__ ker,
    float* __restrict__ out) {
    __shared__ __align__(16) float s_in[IN_ROWS * ROW_F];
    __shared__ __align__(16) float s_k[LL * 16];   // 15 taps + 1 pad per row

    const int tid = threadIdx.x;
    const int tx = tid & 15;     // 16 threads across x, 8 px each
    const int tyi = tid >> 4;    // 8 threads across y, 2 rows each

    const int x0 = blockIdx.x * TW;
    const int y0 = blockIdx.y * TH;
    const int img = blockIdx.z;  // b*3 + c
    const int b = img / CC;

    const float* xin = x + (size_t)img * (HH * WW);

    // kernel taps -> smem, rows padded to 16 floats for LDS.128
    for (int i = tid; i < LL * LL; i += 128) {
        int r = i / LL, c = i - r * LL;
        s_k[r * 16 + c] = ker[b * (LL * LL) + i];
    }

    // input tile: reflect pad + 16B-chunk XOR swizzle
    for (int idx = tid; idx < IN_ROWS * LOAD_F; idx += 128) {
        int r = idx / LOAD_F;
        int f = idx - r * LOAD_F;
        int gy = reflect_idx(y0 + r - PP, HH);
        int gx = reflect_idx(x0 + f - PP, WW);
        float v = xin[gy * WW + gx];
        int p = f >> 2;
        int q = p ^ ((p >> 3) & 7);
        s_in[r * ROW_F + (q << 2) + (f & 3)] = v;
    }
    __syncthreads();

    // swizzled float offsets of this thread's 6 window chunks
    int woff[6];
#pragma unroll
    for (int j = 0; j < 6; j++) {
        int c = 2 * tx + j;
        woff[j] = (c ^ ((c >> 3) & 7)) << 2;
    }

    const float* rowbase = s_in + (size_t)(2 * tyi) * ROW_F;

    float accA[8], accB[8];
#pragma unroll
    for (int i = 0; i < 8; i++) { accA[i] = 0.f; accB[i] = 0.f; }

    float w[24], tE[16], tO[16];

#define LOADW(r)                                                          \
    {                                                                     \
        const float* rp_ = rowbase + (r) * ROW_F;                         \
        _Pragma("unroll") for (int j = 0; j < 6; j++) {                   \
            float4 v_ = *reinterpret_cast<const float4*>(rp_ + woff[j]);  \
            w[4 * j + 0] = v_.x; w[4 * j + 1] = v_.y;                     \
            w[4 * j + 2] = v_.z; w[4 * j + 3] = v_.w;                     \
        }                                                                 \
    }

#define LOADT(t, r)                                                       \
    {                                                                     \
        const float4* k4_ = reinterpret_cast<const float4*>(s_k + (r) * 16); \
        _Pragma("unroll") for (int j = 0; j < 4; j++) {                   \
            float4 v_ = k4_[j];                                           \
            (t)[4 * j + 0] = v_.x; (t)[4 * j + 1] = v_.y;                 \
            (t)[4 * j + 2] = v_.z; (t)[4 * j + 3] = v_.w;                 \
        }                                                                 \
    }

#define FMA_ONE(acc, t)                                                   \
    _Pragma("unroll") for (int dx = 0; dx < 15; dx++)                     \
        _Pragma("unroll") for (int i = 0; i < 8; i++)                     \
            (acc)[i] = fmaf(w[dx + i], (t)[dx], (acc)[i]);

#define FMA_TWO(t_a, t_b)                                                 \
    _Pragma("unroll") for (int dx = 0; dx < 15; dx++)                     \
        _Pragma("unroll") for (int i = 0; i < 8; i++) {                   \
            accA[i] = fmaf(w[dx + i], (t_a)[dx], accA[i]);                \
            accB[i] = fmaf(w[dx + i], (t_b)[dx], accB[i]);                \
        }

    // r = 0: only out-row A (kernel row 0)
    LOADW(0);
    LOADT(tE, 0);
    FMA_ONE(accA, tE);

    // r = 1..14 as 7 parity pairs; accA uses ker[r], accB uses ker[r-1]
#pragma unroll 1
    for (int rp = 0; rp < 7; rp++) {
        int r = 2 * rp + 1;
        LOADW(r);
        LOADT(tO, r);
        FMA_TWO(tO, tE);
        LOADW(r + 1);
        LOADT(tE, r + 1);
        FMA_TWO(tE, tO);
    }

    // r = 15: only out-row B (kernel row 14 == tE loaded at r=14)
    LOADW(15);
    FMA_ONE(accB, tE);

    // direct coalesced stores: 16 lanes x 32B = contiguous 512B per row
    float* o = out + (size_t)img * (HH * WW) + (size_t)(y0 + 2 * tyi) * WW +
               x0 + 8 * tx;
    *reinterpret_cast<float4*>(o) = make_float4(accA[0], accA[1], accA[2], accA[3]);
    *reinterpret_cast<float4*>(o + 4) = make_float4(accA[4], accA[5], accA[6], accA[7]);
    *reinterpret_cast<float4*>(o + WW) = make_float4(accB[0], accB[1], accB[2], accB[3]);
    *reinterpret_cast<float4*>(o + WW + 4) = make_float4(accB[4], accB[5], accB[6], accB[7]);
}

extern "C" void kernel_launch(void* const* d_in, const int* in_sizes, int n_in,
                              void* d_out, int out_size) {
    const float* x = (const float*)d_in[0];
    const float* k = (const float*)d_in[1];
    float* out = (float*)d_out;
    dim3 grid(WW / TW, HH / TH, BB * CC);
    batchblur_kernel<<<grid, 128>>>(x, k, out);
}